// round 12
// baseline (speedup 1.0000x reference)
#include <cuda_runtime.h>
#include <cuda_bf16.h>
#include <math.h>
#include <cstdint>

// ---------------------------------------------------------------------------
// Problem constants
// ---------------------------------------------------------------------------
#define T_TOK 2048
#define D_MODEL 3584
#define HQ 28
#define HKV 4
#define DH 128
#define QKV_OUT ((HQ + 2*HKV) * DH)   // 4608
#define ATTN_DIM (HQ * DH)            // 3584
#define GQA_G (HQ / HKV)              // 7
#define SM_SCALE 0.08838834764831845f // 1/sqrt(128)

// ---------------------------------------------------------------------------
// Scratch
// ---------------------------------------------------------------------------
__device__ float g_qkv[T_TOK * QKV_OUT];    // 2048 x 4608 fp32 (pre-rope)
__device__ float g_rope_cos[T_TOK * (DH/2)];
__device__ float g_rope_sin[T_TOK * (DH/2)];

__device__ __nv_bfloat16 g_X_hi[T_TOK * D_MODEL];      // hidden, [M][K]
__device__ __nv_bfloat16 g_X_lo[T_TOK * D_MODEL];
__device__ __nv_bfloat16 g_A_hi[T_TOK * ATTN_DIM];     // attn out, [M][K]
__device__ __nv_bfloat16 g_A_lo[T_TOK * ATTN_DIM];
__device__ __nv_bfloat16 g_Wq_hi[QKV_OUT * D_MODEL];   // W_qkv^T, [N][K]
__device__ __nv_bfloat16 g_Wq_lo[QKV_OUT * D_MODEL];
__device__ __nv_bfloat16 g_Wo_hi[D_MODEL * ATTN_DIM];  // W_o^T, [N][K]
__device__ __nv_bfloat16 g_Wo_lo[D_MODEL * ATTN_DIM];

__device__ __nv_bfloat16 g_Qhi[HQ * T_TOK * DH];   // [h][t][d]
__device__ __nv_bfloat16 g_Qlo[HQ * T_TOK * DH];
__device__ __nv_bfloat16 g_Khi[HKV * T_TOK * DH];  // [h][t][d]
__device__ __nv_bfloat16 g_Klo[HKV * T_TOK * DH];
__device__ __nv_bfloat16 g_Vthi[HKV * DH * T_TOK]; // [h][d][t] (transposed)
__device__ __nv_bfloat16 g_Vtlo[HKV * DH * T_TOK];

// ---------------------------------------------------------------------------
// Helpers
// ---------------------------------------------------------------------------
__device__ __forceinline__ uint32_t smem_u32(const void* p) {
    uint32_t a;
    asm("{ .reg .u64 t; cvta.to.shared.u64 t, %1; cvt.u32.u64 %0, t; }"
        : "=r"(a) : "l"(p));
    return a;
}

__device__ __forceinline__ uint32_t lds_u32(uint32_t a) {
    uint32_t v;
    asm volatile("ld.shared.b32 %0, [%1];" : "=r"(v) : "r"(a));
    return v;
}

#define CP_ASYNC16(saddr, gptr) \
    asm volatile("cp.async.cg.shared.global [%0], [%1], 16;" \
                 :: "r"(saddr), "l"(gptr))
#define CP_COMMIT() asm volatile("cp.async.commit_group;" ::: "memory")
#define CP_WAIT(n)  asm volatile("cp.async.wait_group %0;" :: "n"(n) : "memory")

#define LDMX4(R, addr) \
    asm volatile("ldmatrix.sync.aligned.m8n8.x4.shared.b16 {%0,%1,%2,%3}, [%4];" \
                 : "=r"((R)[0]), "=r"((R)[1]), "=r"((R)[2]), "=r"((R)[3]) \
                 : "r"(addr))

__device__ __forceinline__ void mma_bf16(float* c, const uint32_t* a,
                                         const uint32_t* b) {
    asm volatile(
        "mma.sync.aligned.m16n8k16.row.col.f32.bf16.bf16.f32 "
        "{%0,%1,%2,%3}, {%4,%5,%6,%7}, {%8,%9}, {%0,%1,%2,%3};"
        : "+f"(c[0]), "+f"(c[1]), "+f"(c[2]), "+f"(c[3])
        : "r"(a[0]), "r"(a[1]), "r"(a[2]), "r"(a[3]),
          "r"(b[0]), "r"(b[1]));
}

__device__ __forceinline__ uint32_t pack_bf16x2(float lo, float hi) {
    __nv_bfloat162 h = __floats2bfloat162_rn(lo, hi);   // x=lo (low 16 bits)
    return *reinterpret_cast<uint32_t*>(&h);
}
__device__ __forceinline__ float bf_res(float f) {
    return f - __bfloat162float(__float2bfloat16(f));
}

// ---------------------------------------------------------------------------
// Prep kernels
// ---------------------------------------------------------------------------
__global__ void convert_split_kernel(const float* __restrict__ in,
                                     __nv_bfloat16* __restrict__ hi,
                                     __nv_bfloat16* __restrict__ lo, int n2)
{
    int i = blockIdx.x * blockDim.x + threadIdx.x;
    if (i >= n2) return;
    float2 v = ((const float2*)in)[i];
    __nv_bfloat16 h0 = __float2bfloat16(v.x);
    __nv_bfloat16 h1 = __float2bfloat16(v.y);
    __nv_bfloat162 hh; hh.x = h0; hh.y = h1;
    __nv_bfloat162 ll;
    ll.x = __float2bfloat16(v.x - __bfloat162float(h0));
    ll.y = __float2bfloat16(v.y - __bfloat162float(h1));
    ((__nv_bfloat162*)hi)[i] = hh;
    ((__nv_bfloat162*)lo)[i] = ll;
}

__global__ void transpose_split_kernel(const float* __restrict__ in,
                                       __nv_bfloat16* __restrict__ hi,
                                       __nv_bfloat16* __restrict__ lo,
                                       int R, int C)
{
    __shared__ float t[32][33];
    int c0 = blockIdx.x * 32, r0 = blockIdx.y * 32;
    int tx = threadIdx.x, ty = threadIdx.y;
    #pragma unroll
    for (int j = ty; j < 32; j += 8)
        t[j][tx] = in[(size_t)(r0 + j) * C + c0 + tx];
    __syncthreads();
    #pragma unroll
    for (int j = ty; j < 32; j += 8) {
        float v = t[tx][j];
        __nv_bfloat16 h = __float2bfloat16(v);
        size_t o = (size_t)(c0 + j) * R + r0 + tx;
        hi[o] = h;
        lo[o] = __float2bfloat16(v - __bfloat162float(h));
    }
}

// ---------------------------------------------------------------------------
// mma.sync bf16x3 GEMM: C[M,N] = A[M,K] @ B[N,K]^T (+bias), fp32 out
// Block 128x128, BK=32, 8 warps, 2-stage cp.async pipeline, 2 CTAs/SM.
// Fragment loads via ldmatrix.x4.
// ---------------------------------------------------------------------------
#define GSTAGE 40960
#define GEMM_SMEM (2 * GSTAGE)

__global__ __launch_bounds__(256, 2) void gemm_mma_bf16x3(
    const __nv_bfloat16* __restrict__ Ahi, const __nv_bfloat16* __restrict__ Alo,
    const __nv_bfloat16* __restrict__ Bhi, const __nv_bfloat16* __restrict__ Blo,
    const float* __restrict__ bias, float* __restrict__ C,
    int M, int N, int K)
{
    extern __shared__ char dsm[];
    const int tid  = threadIdx.x;
    const int lane = tid & 31, wid = tid >> 5;
    const int wm = wid & 3;
    const int wn = wid >> 2;
    const int g  = lane >> 2, t = lane & 3;
    const int m0 = blockIdx.y * 128, n0 = blockIdx.x * 128;

    const uint32_t sbase = smem_u32(dsm);
    const int  lrow = lane & 15;
    const uint32_t lch = (uint32_t)((lane >> 4) * 16);

    float acc[2][8][4];
    #pragma unroll
    for (int mt = 0; mt < 2; mt++)
        #pragma unroll
        for (int nt = 0; nt < 8; nt++)
            #pragma unroll
            for (int j = 0; j < 4; j++) acc[mt][nt][j] = 0.0f;

    const int niter = K / 32;

    #define LOAD_STAGE(it) do {                                               \
        int _st = (it) & 1; int _kb = (it) * 32;                              \
        uint32_t _s0 = sbase + _st * GSTAGE;                                  \
        _Pragma("unroll")                                                     \
        for (int _c = tid; _c < 512; _c += 256) {                             \
            int _row = _c >> 2, _c8 = _c & 3;                                 \
            uint32_t _so = (uint32_t)(_row * 80 + _c8 * 16);                  \
            size_t _ga = (size_t)(m0 + _row) * K + _kb + _c8 * 8;             \
            size_t _gb = (size_t)(n0 + _row) * K + _kb + _c8 * 8;             \
            CP_ASYNC16(_s0 + _so,          Ahi + _ga);                        \
            CP_ASYNC16(_s0 + 10240 + _so,  Alo + _ga);                        \
            CP_ASYNC16(_s0 + 20480 + _so,  Bhi + _gb);                        \
            CP_ASYNC16(_s0 + 30720 + _so,  Blo + _gb);                        \
        }                                                                     \
        CP_COMMIT();                                                          \
    } while (0)

    LOAD_STAGE(0);
    LOAD_STAGE(1);

    for (int it = 0; it < niter; it++) {
        CP_WAIT(1);
        __syncthreads();

        const uint32_t s0 = sbase + (it & 1) * GSTAGE;
        #pragma unroll
        for (int ks = 0; ks < 2; ks++) {
            const uint32_t kof = (uint32_t)(ks * 32) + lch;
            const uint32_t aoff = s0 + (uint32_t)((wm * 32 + lrow) * 80) + kof;
            const uint32_t boff = s0 + 20480u +
                                  (uint32_t)((wn * 64 + lrow) * 80) + kof;

            uint32_t ah[2][4], bh[8][2];
            LDMX4(ah[0], aoff);
            LDMX4(ah[1], aoff + 1280u);
            #pragma unroll
            for (int p = 0; p < 4; p++) {
                uint32_t tb[4];
                LDMX4(tb, boff + (uint32_t)(p * 1280));
                bh[2*p][0] = tb[0]; bh[2*p+1][0] = tb[1];
                bh[2*p][1] = tb[2]; bh[2*p+1][1] = tb[3];
            }
            #pragma unroll
            for (int mt = 0; mt < 2; mt++)
                #pragma unroll
                for (int nt = 0; nt < 8; nt++)
                    mma_bf16(acc[mt][nt], ah[mt], bh[nt]);

            {
                uint32_t bl[8][2];
                #pragma unroll
                for (int p = 0; p < 4; p++) {
                    uint32_t tb[4];
                    LDMX4(tb, boff + 10240u + (uint32_t)(p * 1280));
                    bl[2*p][0] = tb[0]; bl[2*p+1][0] = tb[1];
                    bl[2*p][1] = tb[2]; bl[2*p+1][1] = tb[3];
                }
                #pragma unroll
                for (int mt = 0; mt < 2; mt++)
                    #pragma unroll
                    for (int nt = 0; nt < 8; nt++)
                        mma_bf16(acc[mt][nt], ah[mt], bl[nt]);
            }

            uint32_t al[2][4];
            LDMX4(al[0], aoff + 10240u);
            LDMX4(al[1], aoff + 10240u + 1280u);
            #pragma unroll
            for (int mt = 0; mt < 2; mt++)
                #pragma unroll
                for (int nt = 0; nt < 8; nt++)
                    mma_bf16(acc[mt][nt], al[mt], bh[nt]);
        }
        __syncthreads();

        if (it + 2 < niter) LOAD_STAGE(it + 2);
        else CP_COMMIT();
    }

    const bool hasb = (bias != nullptr);
    #pragma unroll
    for (int mt = 0; mt < 2; mt++) {
        int row0 = m0 + wm * 32 + mt * 16 + g;
        #pragma unroll
        for (int nt = 0; nt < 8; nt++) {
            int col = n0 + wn * 64 + nt * 8 + t * 2;
            float bx = hasb ? bias[col] : 0.0f;
            float by = hasb ? bias[col + 1] : 0.0f;
            float2 v0, v1;
            v0.x = acc[mt][nt][0] + bx; v0.y = acc[mt][nt][1] + by;
            v1.x = acc[mt][nt][2] + bx; v1.y = acc[mt][nt][3] + by;
            *(float2*)(C + (size_t)row0 * N + col) = v0;
            *(float2*)(C + (size_t)(row0 + 8) * N + col) = v1;
        }
    }
    #undef LOAD_STAGE
}

// ---------------------------------------------------------------------------
// RoPE table + Q/K rope-split + V transpose-split
// ---------------------------------------------------------------------------
__global__ void rope_table_kernel(const int* __restrict__ positions)
{
    int idx = blockIdx.x * blockDim.x + threadIdx.x;
    if (idx >= T_TOK * (DH/2)) return;
    int t = idx >> 6;
    int i = idx & 63;
    double inv = pow(1.0e6, -(double)i / 64.0);
    double ang = (double)positions[t] * inv;
    g_rope_cos[idx] = (float)cos(ang);
    g_rope_sin[idx] = (float)sin(ang);
}

__global__ void ropesplit_qk_kernel(const float* __restrict__ qkv)
{
    int t = blockIdx.x;
    int head = blockIdx.y * blockDim.y + threadIdx.y;  // 0..31
    int i = threadIdx.x;                               // 0..63
    float c = g_rope_cos[t * 64 + i];
    float s = g_rope_sin[t * 64 + i];
    size_t src = (size_t)t * QKV_OUT + head * DH;
    float x1 = qkv[src + i];
    float x2 = qkv[src + 64 + i];
    float y1 = x1 * c - x2 * s;
    float y2 = x2 * c + x1 * s;
    __nv_bfloat16 h1 = __float2bfloat16(y1);
    __nv_bfloat16 h2 = __float2bfloat16(y2);
    if (head < HQ) {
        size_t base = ((size_t)head * T_TOK + t) * DH;
        g_Qhi[base + i]      = h1;
        g_Qlo[base + i]      = __float2bfloat16(y1 - __bfloat162float(h1));
        g_Qhi[base + 64 + i] = h2;
        g_Qlo[base + 64 + i] = __float2bfloat16(y2 - __bfloat162float(h2));
    } else {
        size_t base = ((size_t)(head - HQ) * T_TOK + t) * DH;
        g_Khi[base + i]      = h1;
        g_Klo[base + i]      = __float2bfloat16(y1 - __bfloat162float(h1));
        g_Khi[base + 64 + i] = h2;
        g_Klo[base + 64 + i] = __float2bfloat16(y2 - __bfloat162float(h2));
    }
}

__global__ void vsplit_t_kernel(const float* __restrict__ qkv)
{
    __shared__ float tl[32][33];
    int t0 = blockIdx.x * 32, dg0 = blockIdx.y * 32;
    int tx = threadIdx.x, ty = threadIdx.y;
    #pragma unroll
    for (int j = ty; j < 32; j += 8)
        tl[j][tx] = qkv[(size_t)(t0 + j) * QKV_OUT + 4096 + dg0 + tx];
    __syncthreads();
    #pragma unroll
    for (int j = ty; j < 32; j += 8) {
        float v = tl[tx][j];
        __nv_bfloat16 h = __float2bfloat16(v);
        size_t o = (size_t)(dg0 + j) * T_TOK + t0 + tx;
        g_Vthi[o] = h;
        g_Vtlo[o] = __float2bfloat16(v - __bfloat162float(h));
    }
}

// ---------------------------------------------------------------------------
// Tensor-core flash attention (bf16x3 on both GEMMs), causal, GQA.
// Block: 128 q-rows x 1 head. 8 warps, each owns 16 q-rows. KV block 64.
// ---------------------------------------------------------------------------
#define AQ_BYTES   34816                 // 128*272
#define ASTAGE     71680                 // 2*64*272 + 2*128*144
#define ATT_SMEM   (2*AQ_BYTES + 2*ASTAGE)   // 212992

__global__ __launch_bounds__(256, 1) void attn_mma_kernel(
    const __nv_bfloat16* __restrict__ Qhi, const __nv_bfloat16* __restrict__ Qlo,
    const __nv_bfloat16* __restrict__ Khi, const __nv_bfloat16* __restrict__ Klo,
    const __nv_bfloat16* __restrict__ Vthi, const __nv_bfloat16* __restrict__ Vtlo,
    __nv_bfloat16* __restrict__ Ohi, __nv_bfloat16* __restrict__ Olo)
{
    extern __shared__ char dsm[];
    const uint32_t sb = smem_u32(dsm);
    const uint32_t uQhi = sb, uQlo = sb + AQ_BYTES;
    const uint32_t stage0 = sb + 2 * AQ_BYTES;

    const int qb = blockIdx.x;
    const int h  = blockIdx.y;
    const int kvh = h / GQA_G;
    const int q0 = qb * 128;
    const int tid = threadIdx.x;
    const int w = tid >> 5, lane = tid & 31;
    const int g = lane >> 2, t = lane & 3;

    for (int c = tid; c < 4096; c += 256) {
        int half = (c < 2048) ? 0 : 1;
        int j = c & 2047;
        int r = j >> 4, ch = j & 15;
        uint32_t sa = (half ? uQlo : uQhi) + (uint32_t)(r * 272 + ch * 16);
        const __nv_bfloat16* src = half ? Qlo : Qhi;
        CP_ASYNC16(sa, src + ((size_t)(h * T_TOK + q0 + r) * DH + ch * 8));
    }
    CP_COMMIT();

    const int nkb = 2 * qb + 2;

    #define LOADKV(kb_) do {                                                      \
        uint32_t _st = stage0 + ((kb_) & 1) * ASTAGE;                             \
        const int _kv0 = (kb_) * 64;                                              \
        for (int _c = tid; _c < 4096; _c += 256) {                                \
            if (_c < 2048) {                                                      \
                int _lo = (_c >= 1024); int _j = _c & 1023;                       \
                int _r = _j >> 4, _ch = _j & 15;                                  \
                uint32_t _sa = _st + (_lo ? 17408u : 0u)                          \
                             + (uint32_t)(_r * 272 + _ch * 16);                   \
                const __nv_bfloat16* _s = _lo ? Klo : Khi;                        \
                CP_ASYNC16(_sa, _s + ((size_t)(kvh * T_TOK + _kv0 + _r) * DH      \
                                      + _ch * 8));                                \
            } else {                                                              \
                int _i = _c - 2048;                                               \
                int _lo = (_i >= 1024); int _j = _i & 1023;                       \
                int _d = _j >> 3, _ch = _j & 7;                                   \
                uint32_t _sa = _st + 34816u + (_lo ? 18432u : 0u)                 \
                             + (uint32_t)(_d * 144 + _ch * 16);                   \
                const __nv_bfloat16* _s = _lo ? Vtlo : Vthi;                      \
                CP_ASYNC16(_sa, _s + ((size_t)(kvh * DH + _d) * T_TOK             \
                                      + _kv0 + _ch * 8));                         \
            }                                                                     \
        }                                                                         \
        CP_COMMIT();                                                              \
    } while (0)

    LOADKV(0);
    LOADKV(1);

    float o_[16][4];
    #pragma unroll
    for (int v = 0; v < 16; v++)
        #pragma unroll
        for (int j = 0; j < 4; j++) o_[v][j] = 0.0f;
    float m0 = -1e30f, m1 = -1e30f, l0 = 0.0f, l1 = 0.0f;

    const int qrow0 = q0 + w * 16 + g;
    const int qrow1 = qrow0 + 8;

    for (int kb = 0; kb < nkb; kb++) {
        CP_WAIT(1);
        __syncthreads();

        const uint32_t stK = stage0 + (kb & 1) * ASTAGE;
        const uint32_t stV = stK + 34816u;
        const bool skip = (kb == 2 * qb + 1) && (w < 4);

        if (!skip) {
            // ---- S = Q K^T (bf16x3) ----
            float s[8][4];
            #pragma unroll
            for (int j = 0; j < 8; j++)
                #pragma unroll
                for (int r = 0; r < 4; r++) s[j][r] = 0.0f;

            const uint32_t aQh0 = uQhi + (uint32_t)((w * 16 + g) * 272 + t * 4);
            const uint32_t aQl0 = uQlo + (uint32_t)((w * 16 + g) * 272 + t * 4);
            const uint32_t bK0  = stK + (uint32_t)(g * 272 + t * 4);

            #pragma unroll 1
            for (int kk = 0; kk < 8; kk++) {
                uint32_t aqh[4], aql[4];
                uint32_t qa = aQh0 + kk * 32;
                aqh[0] = lds_u32(qa);        aqh[1] = lds_u32(qa + 2176);
                aqh[2] = lds_u32(qa + 16);   aqh[3] = lds_u32(qa + 2192);
                uint32_t ql = aQl0 + kk * 32;
                aql[0] = lds_u32(ql);        aql[1] = lds_u32(ql + 2176);
                aql[2] = lds_u32(ql + 16);   aql[3] = lds_u32(ql + 2192);

                #pragma unroll
                for (int j = 0; j < 8; j++) {
                    uint32_t kb_off = bK0 + (uint32_t)(j * 8 * 272) + kk * 32;
                    uint32_t bkh[2], bkl[2];
                    bkh[0] = lds_u32(kb_off);
                    bkh[1] = lds_u32(kb_off + 16);
                    bkl[0] = lds_u32(kb_off + 17408);
                    bkl[1] = lds_u32(kb_off + 17424);
                    mma_bf16(s[j], aqh, bkh);
                    mma_bf16(s[j], aqh, bkl);
                    mma_bf16(s[j], aql, bkh);
                }
            }

            // ---- scale + causal mask ----
            const bool pmask = (kb >= 2 * qb);
            #pragma unroll
            for (int j = 0; j < 8; j++) {
                #pragma unroll
                for (int r = 0; r < 4; r++) {
                    float v = s[j][r] * SM_SCALE;
                    if (pmask) {
                        int col = kb * 64 + j * 8 + 2 * t + (r & 1);
                        int row = (r < 2) ? qrow0 : qrow1;
                        if (col > row) v = -1e9f;
                    }
                    s[j][r] = v;
                }
            }

            // ---- online softmax ----
            float mx0 = -1e30f, mx1 = -1e30f;
            #pragma unroll
            for (int j = 0; j < 8; j++) {
                mx0 = fmaxf(mx0, fmaxf(s[j][0], s[j][1]));
                mx1 = fmaxf(mx1, fmaxf(s[j][2], s[j][3]));
            }
            mx0 = fmaxf(mx0, __shfl_xor_sync(0xffffffffu, mx0, 1));
            mx0 = fmaxf(mx0, __shfl_xor_sync(0xffffffffu, mx0, 2));
            mx1 = fmaxf(mx1, __shfl_xor_sync(0xffffffffu, mx1, 1));
            mx1 = fmaxf(mx1, __shfl_xor_sync(0xffffffffu, mx1, 2));

            float mn0 = fmaxf(m0, mx0), mn1 = fmaxf(m1, mx1);
            float a0 = __expf(m0 - mn0), a1 = __expf(m1 - mn1);
            m0 = mn0; m1 = mn1;

            float rs0 = 0.0f, rs1 = 0.0f;
            #pragma unroll
            for (int j = 0; j < 8; j++) {
                s[j][0] = __expf(s[j][0] - mn0);
                s[j][1] = __expf(s[j][1] - mn0);
                s[j][2] = __expf(s[j][2] - mn1);
                s[j][3] = __expf(s[j][3] - mn1);
                rs0 += s[j][0] + s[j][1];
                rs1 += s[j][2] + s[j][3];
            }
            rs0 += __shfl_xor_sync(0xffffffffu, rs0, 1);
            rs0 += __shfl_xor_sync(0xffffffffu, rs0, 2);
            rs1 += __shfl_xor_sync(0xffffffffu, rs1, 1);
            rs1 += __shfl_xor_sync(0xffffffffu, rs1, 2);
            l0 = l0 * a0 + rs0;
            l1 = l1 * a1 + rs1;

            #pragma unroll
            for (int v = 0; v < 16; v++) {
                o_[v][0] *= a0; o_[v][1] *= a0;
                o_[v][2] *= a1; o_[v][3] *= a1;
            }

            // ---- pack P into A-fragments (hi/lo) ----
            uint32_t aPhi[4][4], aPlo[4][4];
            #pragma unroll
            for (int u = 0; u < 4; u++) {
                aPhi[u][0] = pack_bf16x2(s[2*u][0],   s[2*u][1]);
                aPhi[u][1] = pack_bf16x2(s[2*u][2],   s[2*u][3]);
                aPhi[u][2] = pack_bf16x2(s[2*u+1][0], s[2*u+1][1]);
                aPhi[u][3] = pack_bf16x2(s[2*u+1][2], s[2*u+1][3]);
                aPlo[u][0] = pack_bf16x2(bf_res(s[2*u][0]),   bf_res(s[2*u][1]));
                aPlo[u][1] = pack_bf16x2(bf_res(s[2*u][2]),   bf_res(s[2*u][3]));
                aPlo[u][2] = pack_bf16x2(bf_res(s[2*u+1][0]), bf_res(s[2*u+1][1]));
                aPlo[u][3] = pack_bf16x2(bf_res(s[2*u+1][2]), bf_res(s[2*u+1][3]));
            }

            // ---- O += P V (bf16x3) ----
            const uint32_t bV0 = stV + (uint32_t)(g * 144 + t * 4);
            #pragma unroll
            for (int v = 0; v < 16; v++) {
                uint32_t vb = bV0 + (uint32_t)(v * 8 * 144);
                #pragma unroll
                for (int u = 0; u < 4; u++) {
                    uint32_t va = vb + u * 32;
                    uint32_t bh[2], bl[2];
                    bh[0] = lds_u32(va);
                    bh[1] = lds_u32(va + 16);
                    bl[0] = lds_u32(va + 18432);
                    bl[1] = lds_u32(va + 18448);
                    mma_bf16(o_[v], aPhi[u], bh);
                    mma_bf16(o_[v], aPhi[u], bl);
                    mma_bf16(o_[v], aPlo[u], bh);
                }
            }
        }

        __syncthreads();
        if (kb + 2 < nkb) LOADKV(kb + 2);
        else CP_COMMIT();
    }

    // ---- epilogue ----
    float inv0 = 1.0f / l0, inv1 = 1.0f / l1;
    #pragma unroll
    for (int v = 0; v < 16; v++) {
        int d = v * 8 + 2 * t;
        float c0 = o_[v][0] * inv0, c1 = o_[v][1] * inv0;
        float c2 = o_[v][2] * inv1, c3 = o_[v][3] * inv1;
        size_t off0 = (size_t)qrow0 * ATTN_DIM + h * DH + d;
        size_t off1 = (size_t)qrow1 * ATTN_DIM + h * DH + d;
        *(uint32_t*)(Ohi + off0) = pack_bf16x2(c0, c1);
        *(uint32_t*)(Olo + off0) = pack_bf16x2(bf_res(c0), bf_res(c1));
        *(uint32_t*)(Ohi + off1) = pack_bf16x2(c2, c3);
        *(uint32_t*)(Olo + off1) = pack_bf16x2(bf_res(c2), bf_res(c3));
    }
    #undef LOADKV
}

// ---------------------------------------------------------------------------
// Launch
// ---------------------------------------------------------------------------
extern "C" void kernel_launch(void* const* d_in, const int* in_sizes, int n_in,
                              void* d_out, int out_size)
{
    const int*   positions = (const int*)  d_in[0];
    const float* hidden    = (const float*)d_in[1];
    const float* W_qkv     = (const float*)d_in[2];
    const float* b_qkv     = (const float*)d_in[3];
    const float* W_o       = (const float*)d_in[4];
    float* out = (float*)d_out;

    float* qkv;  cudaGetSymbolAddress((void**)&qkv, g_qkv);
    __nv_bfloat16 *Xhi, *Xlo, *Ahi, *Alo, *Wqh, *Wql, *Woh, *Wol;
    __nv_bfloat16 *Qhi, *Qlo, *Khi, *Klo, *Vthi, *Vtlo;
    cudaGetSymbolAddress((void**)&Xhi, g_X_hi);
    cudaGetSymbolAddress((void**)&Xlo, g_X_lo);
    cudaGetSymbolAddress((void**)&Ahi, g_A_hi);
    cudaGetSymbolAddress((void**)&Alo, g_A_lo);
    cudaGetSymbolAddress((void**)&Wqh, g_Wq_hi);
    cudaGetSymbolAddress((void**)&Wql, g_Wq_lo);
    cudaGetSymbolAddress((void**)&Woh, g_Wo_hi);
    cudaGetSymbolAddress((void**)&Wol, g_Wo_lo);
    cudaGetSymbolAddress((void**)&Qhi, g_Qhi);
    cudaGetSymbolAddress((void**)&Qlo, g_Qlo);
    cudaGetSymbolAddress((void**)&Khi, g_Khi);
    cudaGetSymbolAddress((void**)&Klo, g_Klo);
    cudaGetSymbolAddress((void**)&Vthi, g_Vthi);
    cudaGetSymbolAddress((void**)&Vtlo, g_Vtlo);

    cudaFuncSetAttribute(gemm_mma_bf16x3,
                         cudaFuncAttributeMaxDynamicSharedMemorySize, GEMM_SMEM);
    cudaFuncSetAttribute(attn_mma_kernel,
                         cudaFuncAttributeMaxDynamicSharedMemorySize, ATT_SMEM);

    // 0) rope table + hidden/weight splits
    {
        int n = T_TOK * (DH / 2);
        rope_table_kernel<<<(n + 255) / 256, 256>>>(positions);
        int n2 = T_TOK * D_MODEL / 2;
        convert_split_kernel<<<(n2 + 255)/256, 256>>>(hidden, Xhi, Xlo, n2);
        dim3 b1(32, 8);
        dim3 g1(QKV_OUT/32, D_MODEL/32);
        transpose_split_kernel<<<g1, b1>>>(W_qkv, Wqh, Wql, D_MODEL, QKV_OUT);
        dim3 g2(D_MODEL/32, ATTN_DIM/32);
        transpose_split_kernel<<<g2, b1>>>(W_o, Woh, Wol, ATTN_DIM, D_MODEL);
    }

    // 1) QKV projection
    {
        dim3 grid(QKV_OUT / 128, T_TOK / 128);
        gemm_mma_bf16x3<<<grid, 256, GEMM_SMEM>>>(
            Xhi, Xlo, Wqh, Wql, b_qkv, qkv, T_TOK, QKV_OUT, D_MODEL);
    }

    // 2) rope+split Q/K, transpose+split V
    {
        dim3 grid(T_TOK, 8), block(64, 4);
        ropesplit_qk_kernel<<<grid, block>>>(qkv);
        dim3 gv(T_TOK/32, (HKV*DH)/32), bv(32, 8);
        vsplit_t_kernel<<<gv, bv>>>(qkv);
    }

    // 3) tensor-core flash attention -> writes bf16 hi/lo directly
    {
        dim3 grid(T_TOK / 128, HQ);
        attn_mma_kernel<<<grid, 256, ATT_SMEM>>>(
            Qhi, Qlo, Khi, Klo, Vthi, Vtlo, Ahi, Alo);
    }

    // 4) O projection
    {
        dim3 grid(D_MODEL / 128, T_TOK / 128);
        gemm_mma_bf16x3<<<grid, 256, GEMM_SMEM>>>(
            Ahi, Alo, Woh, Wol, nullptr, out, T_TOK, D_MODEL, ATTN_DIM);
    }
}

// round 13
// speedup vs baseline: 1.0088x; 1.0088x over previous
#include <cuda_runtime.h>
#include <cuda_bf16.h>
#include <math.h>
#include <cstdint>

// ---------------------------------------------------------------------------
// Problem constants
// ---------------------------------------------------------------------------
#define T_TOK 2048
#define D_MODEL 3584
#define HQ 28
#define HKV 4
#define DH 128
#define QKV_OUT ((HQ + 2*HKV) * DH)   // 4608
#define ATTN_DIM (HQ * DH)            // 3584
#define GQA_G (HQ / HKV)              // 7
#define SM_SCALE 0.08838834764831845f // 1/sqrt(128)

// ---------------------------------------------------------------------------
// Scratch
// ---------------------------------------------------------------------------
__device__ float g_rope_cos[T_TOK * (DH/2)];
__device__ float g_rope_sin[T_TOK * (DH/2)];

__device__ __nv_bfloat16 g_X_hi[T_TOK * D_MODEL];      // hidden, [M][K]
__device__ __nv_bfloat16 g_X_lo[T_TOK * D_MODEL];
__device__ __nv_bfloat16 g_A_hi[T_TOK * ATTN_DIM];     // attn out, [M][K]
__device__ __nv_bfloat16 g_A_lo[T_TOK * ATTN_DIM];
__device__ __nv_bfloat16 g_Wq_hi[QKV_OUT * D_MODEL];   // W_qkv^T, [N][K]
__device__ __nv_bfloat16 g_Wq_lo[QKV_OUT * D_MODEL];
__device__ __nv_bfloat16 g_Wo_hi[D_MODEL * ATTN_DIM];  // W_o^T, [N][K]
__device__ __nv_bfloat16 g_Wo_lo[D_MODEL * ATTN_DIM];

__device__ __nv_bfloat16 g_Qhi[HQ * T_TOK * DH];   // [h][t][d]
__device__ __nv_bfloat16 g_Qlo[HQ * T_TOK * DH];
__device__ __nv_bfloat16 g_Khi[HKV * T_TOK * DH];  // [h][t][d]
__device__ __nv_bfloat16 g_Klo[HKV * T_TOK * DH];
__device__ __nv_bfloat16 g_Vthi[HKV * DH * T_TOK]; // [h][d][t] (transposed)
__device__ __nv_bfloat16 g_Vtlo[HKV * DH * T_TOK];

// ---------------------------------------------------------------------------
// Helpers
// ---------------------------------------------------------------------------
__device__ __forceinline__ uint32_t smem_u32(const void* p) {
    uint32_t a;
    asm("{ .reg .u64 t; cvta.to.shared.u64 t, %1; cvt.u32.u64 %0, t; }"
        : "=r"(a) : "l"(p));
    return a;
}

__device__ __forceinline__ uint32_t lds_u32(uint32_t a) {
    uint32_t v;
    asm volatile("ld.shared.b32 %0, [%1];" : "=r"(v) : "r"(a));
    return v;
}

#define CP_ASYNC16(saddr, gptr) \
    asm volatile("cp.async.cg.shared.global [%0], [%1], 16;" \
                 :: "r"(saddr), "l"(gptr))
#define CP_COMMIT() asm volatile("cp.async.commit_group;" ::: "memory")
#define CP_WAIT(n)  asm volatile("cp.async.wait_group %0;" :: "n"(n) : "memory")

__device__ __forceinline__ void mma_bf16(float* c, const uint32_t* a,
                                         const uint32_t* b) {
    asm volatile(
        "mma.sync.aligned.m16n8k16.row.col.f32.bf16.bf16.f32 "
        "{%0,%1,%2,%3}, {%4,%5,%6,%7}, {%8,%9}, {%0,%1,%2,%3};"
        : "+f"(c[0]), "+f"(c[1]), "+f"(c[2]), "+f"(c[3])
        : "r"(a[0]), "r"(a[1]), "r"(a[2]), "r"(a[3]),
          "r"(b[0]), "r"(b[1]));
}

__device__ __forceinline__ uint32_t pack_bf16x2(float lo, float hi) {
    __nv_bfloat162 h = __floats2bfloat162_rn(lo, hi);   // x=lo (low 16 bits)
    return *reinterpret_cast<uint32_t*>(&h);
}
__device__ __forceinline__ float bf_res(float f) {
    return f - __bfloat162float(__float2bfloat16(f));
}

// ---------------------------------------------------------------------------
// Prep kernels
// ---------------------------------------------------------------------------
__global__ void convert_split_kernel(const float* __restrict__ in,
                                     __nv_bfloat16* __restrict__ hi,
                                     __nv_bfloat16* __restrict__ lo, int n2)
{
    int i = blockIdx.x * blockDim.x + threadIdx.x;
    if (i >= n2) return;
    float2 v = ((const float2*)in)[i];
    __nv_bfloat16 h0 = __float2bfloat16(v.x);
    __nv_bfloat16 h1 = __float2bfloat16(v.y);
    __nv_bfloat162 hh; hh.x = h0; hh.y = h1;
    __nv_bfloat162 ll;
    ll.x = __float2bfloat16(v.x - __bfloat162float(h0));
    ll.y = __float2bfloat16(v.y - __bfloat162float(h1));
    ((__nv_bfloat162*)hi)[i] = hh;
    ((__nv_bfloat162*)lo)[i] = ll;
}

__global__ void transpose_split_kernel(const float* __restrict__ in,
                                       __nv_bfloat16* __restrict__ hi,
                                       __nv_bfloat16* __restrict__ lo,
                                       int R, int C)
{
    __shared__ float t[32][33];
    int c0 = blockIdx.x * 32, r0 = blockIdx.y * 32;
    int tx = threadIdx.x, ty = threadIdx.y;
    #pragma unroll
    for (int j = ty; j < 32; j += 8)
        t[j][tx] = in[(size_t)(r0 + j) * C + c0 + tx];
    __syncthreads();
    #pragma unroll
    for (int j = ty; j < 32; j += 8) {
        float v = t[tx][j];
        __nv_bfloat16 h = __float2bfloat16(v);
        size_t o = (size_t)(c0 + j) * R + r0 + tx;
        hi[o] = h;
        lo[o] = __float2bfloat16(v - __bfloat162float(h));
    }
}

// ---------------------------------------------------------------------------
// mma.sync bf16x3 GEMM: C[M,N] = A[M,K] @ B[N,K]^T (+bias), fp32 out
// Block 128x128, BK=32, 8 warps, 2-stage cp.async pipeline, 2 CTAs/SM.
// Optional fused QKV epilogue (rope + bf16 split + V transpose).
// ---------------------------------------------------------------------------
#define GSTAGE 40960
#define GEMM_SMEM (2 * GSTAGE)

__global__ __launch_bounds__(256, 2) void gemm_mma_bf16x3(
    const __nv_bfloat16* __restrict__ Ahi, const __nv_bfloat16* __restrict__ Alo,
    const __nv_bfloat16* __restrict__ Bhi, const __nv_bfloat16* __restrict__ Blo,
    const float* __restrict__ bias, float* __restrict__ C,
    int M, int N, int K,
    __nv_bfloat16* __restrict__ oQhi, __nv_bfloat16* __restrict__ oQlo,
    __nv_bfloat16* __restrict__ oKhi, __nv_bfloat16* __restrict__ oKlo,
    __nv_bfloat16* __restrict__ oVhi, __nv_bfloat16* __restrict__ oVlo)
{
    extern __shared__ char dsm[];
    const int tid  = threadIdx.x;
    const int lane = tid & 31, wid = tid >> 5;
    const int wm = wid & 3;
    const int wn = wid >> 2;
    const int g  = lane >> 2, t = lane & 3;
    const int m0 = blockIdx.y * 128, n0 = blockIdx.x * 128;

    const uint32_t sbase = smem_u32(dsm);

    float acc[2][8][4];
    #pragma unroll
    for (int mt = 0; mt < 2; mt++)
        #pragma unroll
        for (int nt = 0; nt < 8; nt++)
            #pragma unroll
            for (int j = 0; j < 4; j++) acc[mt][nt][j] = 0.0f;

    const int niter = K / 32;

    #define LOAD_STAGE(it) do {                                               \
        int _st = (it) & 1; int _kb = (it) * 32;                              \
        uint32_t _s0 = sbase + _st * GSTAGE;                                  \
        _Pragma("unroll")                                                     \
        for (int _c = tid; _c < 512; _c += 256) {                             \
            int _row = _c >> 2, _c8 = _c & 3;                                 \
            uint32_t _so = (uint32_t)(_row * 80 + _c8 * 16);                  \
            size_t _ga = (size_t)(m0 + _row) * K + _kb + _c8 * 8;             \
            size_t _gb = (size_t)(n0 + _row) * K + _kb + _c8 * 8;             \
            CP_ASYNC16(_s0 + _so,          Ahi + _ga);                        \
            CP_ASYNC16(_s0 + 10240 + _so,  Alo + _ga);                        \
            CP_ASYNC16(_s0 + 20480 + _so,  Bhi + _gb);                        \
            CP_ASYNC16(_s0 + 30720 + _so,  Blo + _gb);                        \
        }                                                                     \
        CP_COMMIT();                                                          \
    } while (0)

    LOAD_STAGE(0);
    LOAD_STAGE(1);

    for (int it = 0; it < niter; it++) {
        CP_WAIT(1);
        __syncthreads();

        const uint32_t s0 = sbase + (it & 1) * GSTAGE;
        #pragma unroll
        for (int ks = 0; ks < 2; ks++) {
            const uint32_t koff = (uint32_t)(ks * 32 + t * 4);
            const uint32_t aB = s0 + (uint32_t)((wm * 32 + g) * 80) + koff;
            const uint32_t bB = s0 + 20480u + (uint32_t)((wn * 64 + g) * 80) + koff;

            uint32_t a[2][4], bhi[8][2], bl[8][2];

            #pragma unroll
            for (int mt = 0; mt < 2; mt++) {
                uint32_t ab = aB + (uint32_t)(mt * 16 * 80);
                a[mt][0] = lds_u32(ab);
                a[mt][1] = lds_u32(ab + 640);
                a[mt][2] = lds_u32(ab + 16);
                a[mt][3] = lds_u32(ab + 656);
            }
            #pragma unroll
            for (int nt = 0; nt < 8; nt++) {
                uint32_t bb = bB + (uint32_t)(nt * 8 * 80);
                bhi[nt][0] = lds_u32(bb);
                bhi[nt][1] = lds_u32(bb + 16);
            }
            #pragma unroll
            for (int mt = 0; mt < 2; mt++)
                #pragma unroll
                for (int nt = 0; nt < 8; nt++)
                    mma_bf16(acc[mt][nt], a[mt], bhi[nt]);

            #pragma unroll
            for (int nt = 0; nt < 8; nt++) {
                uint32_t bb = bB + 10240u + (uint32_t)(nt * 8 * 80);
                bl[nt][0] = lds_u32(bb);
                bl[nt][1] = lds_u32(bb + 16);
            }
            #pragma unroll
            for (int mt = 0; mt < 2; mt++)
                #pragma unroll
                for (int nt = 0; nt < 8; nt++)
                    mma_bf16(acc[mt][nt], a[mt], bl[nt]);

            #pragma unroll
            for (int mt = 0; mt < 2; mt++) {
                uint32_t ab = aB + 10240u + (uint32_t)(mt * 16 * 80);
                a[mt][0] = lds_u32(ab);
                a[mt][1] = lds_u32(ab + 640);
                a[mt][2] = lds_u32(ab + 16);
                a[mt][3] = lds_u32(ab + 656);
            }
            #pragma unroll
            for (int mt = 0; mt < 2; mt++)
                #pragma unroll
                for (int nt = 0; nt < 8; nt++)
                    mma_bf16(acc[mt][nt], a[mt], bhi[nt]);
        }
        __syncthreads();

        if (it + 2 < niter) LOAD_STAGE(it + 2);
        else CP_COMMIT();
    }

    if (oQhi == nullptr) {
        // ---- standard epilogue: write fp32 C (+bias) ----
        const bool hasb = (bias != nullptr);
        #pragma unroll
        for (int mt = 0; mt < 2; mt++) {
            int row0 = m0 + wm * 32 + mt * 16 + g;
            #pragma unroll
            for (int nt = 0; nt < 8; nt++) {
                int col = n0 + wn * 64 + nt * 8 + t * 2;
                float bx = hasb ? bias[col] : 0.0f;
                float by = hasb ? bias[col + 1] : 0.0f;
                float2 v0, v1;
                v0.x = acc[mt][nt][0] + bx; v0.y = acc[mt][nt][1] + by;
                v1.x = acc[mt][nt][2] + bx; v1.y = acc[mt][nt][3] + by;
                *(float2*)(C + (size_t)row0 * N + col) = v0;
                *(float2*)(C + (size_t)(row0 + 8) * N + col) = v1;
            }
        }
    } else {
        // ---- fused QKV epilogue: stage tile, then rope/split/transpose ----
        float* tile = (float*)dsm;   // [128][129] fp32, 66048 B
        __syncthreads();   // all mainloop smem reads done (loop-end sync passed)
        #pragma unroll
        for (int mt = 0; mt < 2; mt++) {
            int r0 = wm * 32 + mt * 16 + g;
            #pragma unroll
            for (int nt = 0; nt < 8; nt++) {
                int col = wn * 64 + nt * 8 + t * 2;
                float bx = bias[n0 + col];
                float by = bias[n0 + col + 1];
                tile[r0 * 129 + col]           = acc[mt][nt][0] + bx;
                tile[r0 * 129 + col + 1]       = acc[mt][nt][1] + by;
                tile[(r0 + 8) * 129 + col]     = acc[mt][nt][2] + bx;
                tile[(r0 + 8) * 129 + col + 1] = acc[mt][nt][3] + by;
            }
        }
        __syncthreads();

        const int nh = blockIdx.x;   // 0..35: 0-27 Q heads, 28-31 K heads, 32-35 V
        if (nh < HQ + HKV) {
            // Q or K: rope + split, layout [head][t][d]
            const bool isQ = (nh < HQ);
            __nv_bfloat16* Hhi = isQ ? oQhi : oKhi;
            __nv_bfloat16* Hlo = isQ ? oQlo : oKlo;
            const int head = isQ ? nh : nh - HQ;
            const int i = tid & 63;
            const int rb = (tid >> 6) * 32;
            #pragma unroll 4
            for (int rr = 0; rr < 32; rr++) {
                int r = rb + rr;
                int gt = m0 + r;
                float c = g_rope_cos[gt * 64 + i];
                float s = g_rope_sin[gt * 64 + i];
                float x1 = tile[r * 129 + i];
                float x2 = tile[r * 129 + i + 64];
                float y1 = x1 * c - x2 * s;
                float y2 = x2 * c + x1 * s;
                size_t base = ((size_t)head * T_TOK + gt) * DH;
                __nv_bfloat16 h1 = __float2bfloat16(y1);
                __nv_bfloat16 h2 = __float2bfloat16(y2);
                Hhi[base + i]      = h1;
                Hlo[base + i]      = __float2bfloat16(y1 - __bfloat162float(h1));
                Hhi[base + 64 + i] = h2;
                Hlo[base + 64 + i] = __float2bfloat16(y2 - __bfloat162float(h2));
            }
        } else {
            // V: split + transpose -> [dg][t]
            const int d  = tid >> 1;
            const int th = (tid & 1) * 64;
            const size_t dg = (size_t)(n0 - (HQ + HKV) * DH) + d;
            #pragma unroll 4
            for (int tt = 0; tt < 64; tt++) {
                int r = th + tt;
                float v = tile[r * 129 + d];
                __nv_bfloat16 h = __float2bfloat16(v);
                size_t o = dg * T_TOK + m0 + r;
                oVhi[o] = h;
                oVlo[o] = __float2bfloat16(v - __bfloat162float(h));
            }
        }
    }
    #undef LOAD_STAGE
}

// ---------------------------------------------------------------------------
// RoPE table
// ---------------------------------------------------------------------------
__global__ void rope_table_kernel(const int* __restrict__ positions)
{
    int idx = blockIdx.x * blockDim.x + threadIdx.x;
    if (idx >= T_TOK * (DH/2)) return;
    int t = idx >> 6;
    int i = idx & 63;
    double inv = pow(1.0e6, -(double)i / 64.0);
    double ang = (double)positions[t] * inv;
    g_rope_cos[idx] = (float)cos(ang);
    g_rope_sin[idx] = (float)sin(ang);
}

// ---------------------------------------------------------------------------
// Tensor-core flash attention (bf16x3 on both GEMMs), causal, GQA.
// Block: 128 q-rows x 1 head. 8 warps, each owns 16 q-rows. KV block 64.
// ---------------------------------------------------------------------------
#define AQ_BYTES   34816                 // 128*272
#define ASTAGE     71680                 // 2*64*272 + 2*128*144
#define ATT_SMEM   (2*AQ_BYTES + 2*ASTAGE)   // 212992

__global__ __launch_bounds__(256, 1) void attn_mma_kernel(
    const __nv_bfloat16* __restrict__ Qhi, const __nv_bfloat16* __restrict__ Qlo,
    const __nv_bfloat16* __restrict__ Khi, const __nv_bfloat16* __restrict__ Klo,
    const __nv_bfloat16* __restrict__ Vthi, const __nv_bfloat16* __restrict__ Vtlo,
    __nv_bfloat16* __restrict__ Ohi, __nv_bfloat16* __restrict__ Olo)
{
    extern __shared__ char dsm[];
    const uint32_t sb = smem_u32(dsm);
    const uint32_t uQhi = sb, uQlo = sb + AQ_BYTES;
    const uint32_t stage0 = sb + 2 * AQ_BYTES;

    const int qb = blockIdx.x;
    const int h  = blockIdx.y;
    const int kvh = h / GQA_G;
    const int q0 = qb * 128;
    const int tid = threadIdx.x;
    const int w = tid >> 5, lane = tid & 31;
    const int g = lane >> 2, t = lane & 3;

    for (int c = tid; c < 4096; c += 256) {
        int half = (c < 2048) ? 0 : 1;
        int j = c & 2047;
        int r = j >> 4, ch = j & 15;
        uint32_t sa = (half ? uQlo : uQhi) + (uint32_t)(r * 272 + ch * 16);
        const __nv_bfloat16* src = half ? Qlo : Qhi;
        CP_ASYNC16(sa, src + ((size_t)(h * T_TOK + q0 + r) * DH + ch * 8));
    }
    CP_COMMIT();

    const int nkb = 2 * qb + 2;

    #define LOADKV(kb_) do {                                                      \
        uint32_t _st = stage0 + ((kb_) & 1) * ASTAGE;                             \
        const int _kv0 = (kb_) * 64;                                              \
        for (int _c = tid; _c < 4096; _c += 256) {                                \
            if (_c < 2048) {                                                      \
                int _lo = (_c >= 1024); int _j = _c & 1023;                       \
                int _r = _j >> 4, _ch = _j & 15;                                  \
                uint32_t _sa = _st + (_lo ? 17408u : 0u)                          \
                             + (uint32_t)(_r * 272 + _ch * 16);                   \
                const __nv_bfloat16* _s = _lo ? Klo : Khi;                        \
                CP_ASYNC16(_sa, _s + ((size_t)(kvh * T_TOK + _kv0 + _r) * DH      \
                                      + _ch * 8));                                \
            } else {                                                              \
                int _i = _c - 2048;                                               \
                int _lo = (_i >= 1024); int _j = _i & 1023;                       \
                int _d = _j >> 3, _ch = _j & 7;                                   \
                uint32_t _sa = _st + 34816u + (_lo ? 18432u : 0u)                 \
                             + (uint32_t)(_d * 144 + _ch * 16);                   \
                const __nv_bfloat16* _s = _lo ? Vtlo : Vthi;                      \
                CP_ASYNC16(_sa, _s + ((size_t)(kvh * DH + _d) * T_TOK             \
                                      + _kv0 + _ch * 8));                         \
            }                                                                     \
        }                                                                         \
        CP_COMMIT();                                                              \
    } while (0)

    LOADKV(0);
    LOADKV(1);

    float o_[16][4];
    #pragma unroll
    for (int v = 0; v < 16; v++)
        #pragma unroll
        for (int j = 0; j < 4; j++) o_[v][j] = 0.0f;
    float m0 = -1e30f, m1 = -1e30f, l0 = 0.0f, l1 = 0.0f;

    const int qrow0 = q0 + w * 16 + g;
    const int qrow1 = qrow0 + 8;

    for (int kb = 0; kb < nkb; kb++) {
        CP_WAIT(1);
        __syncthreads();

        const uint32_t stK = stage0 + (kb & 1) * ASTAGE;
        const uint32_t stV = stK + 34816u;
        const bool skip = (kb == 2 * qb + 1) && (w < 4);

        if (!skip) {
            // ---- S = Q K^T (bf16x3) ----
            float s[8][4];
            #pragma unroll
            for (int j = 0; j < 8; j++)
                #pragma unroll
                for (int r = 0; r < 4; r++) s[j][r] = 0.0f;

            const uint32_t aQh0 = uQhi + (uint32_t)((w * 16 + g) * 272 + t * 4);
            const uint32_t aQl0 = uQlo + (uint32_t)((w * 16 + g) * 272 + t * 4);
            const uint32_t bK0  = stK + (uint32_t)(g * 272 + t * 4);

            #pragma unroll 1
            for (int kk = 0; kk < 8; kk++) {
                uint32_t aqh[4], aql[4];
                uint32_t qa = aQh0 + kk * 32;
                aqh[0] = lds_u32(qa);        aqh[1] = lds_u32(qa + 2176);
                aqh[2] = lds_u32(qa + 16);   aqh[3] = lds_u32(qa + 2192);
                uint32_t ql = aQl0 + kk * 32;
                aql[0] = lds_u32(ql);        aql[1] = lds_u32(ql + 2176);
                aql[2] = lds_u32(ql + 16);   aql[3] = lds_u32(ql + 2192);

                #pragma unroll
                for (int j = 0; j < 8; j++) {
                    uint32_t kb_off = bK0 + (uint32_t)(j * 8 * 272) + kk * 32;
                    uint32_t bkh[2], bkl[2];
                    bkh[0] = lds_u32(kb_off);
                    bkh[1] = lds_u32(kb_off + 16);
                    bkl[0] = lds_u32(kb_off + 17408);
                    bkl[1] = lds_u32(kb_off + 17424);
                    mma_bf16(s[j], aqh, bkh);
                    mma_bf16(s[j], aqh, bkl);
                    mma_bf16(s[j], aql, bkh);
                }
            }

            // ---- scale + causal mask ----
            const bool pmask = (kb >= 2 * qb);
            #pragma unroll
            for (int j = 0; j < 8; j++) {
                #pragma unroll
                for (int r = 0; r < 4; r++) {
                    float v = s[j][r] * SM_SCALE;
                    if (pmask) {
                        int col = kb * 64 + j * 8 + 2 * t + (r & 1);
                        int row = (r < 2) ? qrow0 : qrow1;
                        if (col > row) v = -1e9f;
                    }
                    s[j][r] = v;
                }
            }

            // ---- online softmax ----
            float mx0 = -1e30f, mx1 = -1e30f;
            #pragma unroll
            for (int j = 0; j < 8; j++) {
                mx0 = fmaxf(mx0, fmaxf(s[j][0], s[j][1]));
                mx1 = fmaxf(mx1, fmaxf(s[j][2], s[j][3]));
            }
            mx0 = fmaxf(mx0, __shfl_xor_sync(0xffffffffu, mx0, 1));
            mx0 = fmaxf(mx0, __shfl_xor_sync(0xffffffffu, mx0, 2));
            mx1 = fmaxf(mx1, __shfl_xor_sync(0xffffffffu, mx1, 1));
            mx1 = fmaxf(mx1, __shfl_xor_sync(0xffffffffu, mx1, 2));

            float mn0 = fmaxf(m0, mx0), mn1 = fmaxf(m1, mx1);
            float a0 = __expf(m0 - mn0), a1 = __expf(m1 - mn1);
            m0 = mn0; m1 = mn1;

            float rs0 = 0.0f, rs1 = 0.0f;
            #pragma unroll
            for (int j = 0; j < 8; j++) {
                s[j][0] = __expf(s[j][0] - mn0);
                s[j][1] = __expf(s[j][1] - mn0);
                s[j][2] = __expf(s[j][2] - mn1);
                s[j][3] = __expf(s[j][3] - mn1);
                rs0 += s[j][0] + s[j][1];
                rs1 += s[j][2] + s[j][3];
            }
            rs0 += __shfl_xor_sync(0xffffffffu, rs0, 1);
            rs0 += __shfl_xor_sync(0xffffffffu, rs0, 2);
            rs1 += __shfl_xor_sync(0xffffffffu, rs1, 1);
            rs1 += __shfl_xor_sync(0xffffffffu, rs1, 2);
            l0 = l0 * a0 + rs0;
            l1 = l1 * a1 + rs1;

            #pragma unroll
            for (int v = 0; v < 16; v++) {
                o_[v][0] *= a0; o_[v][1] *= a0;
                o_[v][2] *= a1; o_[v][3] *= a1;
            }

            // ---- pack P into A-fragments (hi/lo) ----
            uint32_t aPhi[4][4], aPlo[4][4];
            #pragma unroll
            for (int u = 0; u < 4; u++) {
                aPhi[u][0] = pack_bf16x2(s[2*u][0],   s[2*u][1]);
                aPhi[u][1] = pack_bf16x2(s[2*u][2],   s[2*u][3]);
                aPhi[u][2] = pack_bf16x2(s[2*u+1][0], s[2*u+1][1]);
                aPhi[u][3] = pack_bf16x2(s[2*u+1][2], s[2*u+1][3]);
                aPlo[u][0] = pack_bf16x2(bf_res(s[2*u][0]),   bf_res(s[2*u][1]));
                aPlo[u][1] = pack_bf16x2(bf_res(s[2*u][2]),   bf_res(s[2*u][3]));
                aPlo[u][2] = pack_bf16x2(bf_res(s[2*u+1][0]), bf_res(s[2*u+1][1]));
                aPlo[u][3] = pack_bf16x2(bf_res(s[2*u+1][2]), bf_res(s[2*u+1][3]));
            }

            // ---- O += P V (bf16x3) ----
            const uint32_t bV0 = stV + (uint32_t)(g * 144 + t * 4);
            #pragma unroll
            for (int v = 0; v < 16; v++) {
                uint32_t vb = bV0 + (uint32_t)(v * 8 * 144);
                #pragma unroll
                for (int u = 0; u < 4; u++) {
                    uint32_t va = vb + u * 32;
                    uint32_t bh[2], bl[2];
                    bh[0] = lds_u32(va);
                    bh[1] = lds_u32(va + 16);
                    bl[0] = lds_u32(va + 18432);
                    bl[1] = lds_u32(va + 18448);
                    mma_bf16(o_[v], aPhi[u], bh);
                    mma_bf16(o_[v], aPhi[u], bl);
                    mma_bf16(o_[v], aPlo[u], bh);
                }
            }
        }

        __syncthreads();
        if (kb + 2 < nkb) LOADKV(kb + 2);
        else CP_COMMIT();
    }

    // ---- epilogue ----
    float inv0 = 1.0f / l0, inv1 = 1.0f / l1;
    #pragma unroll
    for (int v = 0; v < 16; v++) {
        int d = v * 8 + 2 * t;
        float c0 = o_[v][0] * inv0, c1 = o_[v][1] * inv0;
        float c2 = o_[v][2] * inv1, c3 = o_[v][3] * inv1;
        size_t off0 = (size_t)qrow0 * ATTN_DIM + h * DH + d;
        size_t off1 = (size_t)qrow1 * ATTN_DIM + h * DH + d;
        *(uint32_t*)(Ohi + off0) = pack_bf16x2(c0, c1);
        *(uint32_t*)(Olo + off0) = pack_bf16x2(bf_res(c0), bf_res(c1));
        *(uint32_t*)(Ohi + off1) = pack_bf16x2(c2, c3);
        *(uint32_t*)(Olo + off1) = pack_bf16x2(bf_res(c2), bf_res(c3));
    }
    #undef LOADKV
}

// ---------------------------------------------------------------------------
// Launch
// ---------------------------------------------------------------------------
extern "C" void kernel_launch(void* const* d_in, const int* in_sizes, int n_in,
                              void* d_out, int out_size)
{
    const int*   positions = (const int*)  d_in[0];
    const float* hidden    = (const float*)d_in[1];
    const float* W_qkv     = (const float*)d_in[2];
    const float* b_qkv     = (const float*)d_in[3];
    const float* W_o       = (const float*)d_in[4];
    float* out = (float*)d_out;

    __nv_bfloat16 *Xhi, *Xlo, *Ahi, *Alo, *Wqh, *Wql, *Woh, *Wol;
    __nv_bfloat16 *Qhi, *Qlo, *Khi, *Klo, *Vthi, *Vtlo;
    cudaGetSymbolAddress((void**)&Xhi, g_X_hi);
    cudaGetSymbolAddress((void**)&Xlo, g_X_lo);
    cudaGetSymbolAddress((void**)&Ahi, g_A_hi);
    cudaGetSymbolAddress((void**)&Alo, g_A_lo);
    cudaGetSymbolAddress((void**)&Wqh, g_Wq_hi);
    cudaGetSymbolAddress((void**)&Wql, g_Wq_lo);
    cudaGetSymbolAddress((void**)&Woh, g_Wo_hi);
    cudaGetSymbolAddress((void**)&Wol, g_Wo_lo);
    cudaGetSymbolAddress((void**)&Qhi, g_Qhi);
    cudaGetSymbolAddress((void**)&Qlo, g_Qlo);
    cudaGetSymbolAddress((void**)&Khi, g_Khi);
    cudaGetSymbolAddress((void**)&Klo, g_Klo);
    cudaGetSymbolAddress((void**)&Vthi, g_Vthi);
    cudaGetSymbolAddress((void**)&Vtlo, g_Vtlo);

    cudaFuncSetAttribute(gemm_mma_bf16x3,
                         cudaFuncAttributeMaxDynamicSharedMemorySize, GEMM_SMEM);
    cudaFuncSetAttribute(attn_mma_kernel,
                         cudaFuncAttributeMaxDynamicSharedMemorySize, ATT_SMEM);

    // 0) rope table + hidden/weight splits
    {
        int n = T_TOK * (DH / 2);
        rope_table_kernel<<<(n + 255) / 256, 256>>>(positions);
        int n2 = T_TOK * D_MODEL / 2;
        convert_split_kernel<<<(n2 + 255)/256, 256>>>(hidden, Xhi, Xlo, n2);
        dim3 b1(32, 8);
        dim3 g1(QKV_OUT/32, D_MODEL/32);
        transpose_split_kernel<<<g1, b1>>>(W_qkv, Wqh, Wql, D_MODEL, QKV_OUT);
        dim3 g2(D_MODEL/32, ATTN_DIM/32);
        transpose_split_kernel<<<g2, b1>>>(W_o, Woh, Wol, ATTN_DIM, D_MODEL);
    }

    // 1) QKV projection with fused rope/split/transpose epilogue
    {
        dim3 grid(QKV_OUT / 128, T_TOK / 128);
        gemm_mma_bf16x3<<<grid, 256, GEMM_SMEM>>>(
            Xhi, Xlo, Wqh, Wql, b_qkv, nullptr, T_TOK, QKV_OUT, D_MODEL,
            Qhi, Qlo, Khi, Klo, Vthi, Vtlo);
    }

    // 2) tensor-core flash attention -> writes bf16 hi/lo directly
    {
        dim3 grid(T_TOK / 128, HQ);
        attn_mma_kernel<<<grid, 256, ATT_SMEM>>>(
            Qhi, Qlo, Khi, Klo, Vthi, Vtlo, Ahi, Alo);
    }

    // 3) O projection (standard epilogue)
    {
        dim3 grid(D_MODEL / 128, T_TOK / 128);
        gemm_mma_bf16x3<<<grid, 256, GEMM_SMEM>>>(
            Ahi, Alo, Woh, Wol, nullptr, out, T_TOK, D_MODEL, ATTN_DIM,
            nullptr, nullptr, nullptr, nullptr, nullptr, nullptr);
    }
}

// round 15
// speedup vs baseline: 1.0966x; 1.0870x over previous
#include <cuda_runtime.h>
#include <cuda_bf16.h>
#include <math.h>
#include <cstdint>

// ---------------------------------------------------------------------------
// Problem constants
// ---------------------------------------------------------------------------
#define T_TOK 2048
#define D_MODEL 3584
#define HQ 28
#define HKV 4
#define DH 128
#define QKV_OUT ((HQ + 2*HKV) * DH)   // 4608
#define ATTN_DIM (HQ * DH)            // 3584
#define GQA_G (HQ / HKV)              // 7
#define SM_SCALE 0.08838834764831845f // 1/sqrt(128)

// ---------------------------------------------------------------------------
// Scratch
// ---------------------------------------------------------------------------
__device__ float g_qkv[T_TOK * QKV_OUT];    // 2048 x 4608 fp32 (pre-rope)
__device__ float g_rope_cos[T_TOK * (DH/2)];
__device__ float g_rope_sin[T_TOK * (DH/2)];

__device__ __nv_bfloat16 g_X_hi[T_TOK * D_MODEL];      // hidden, [M][K]
__device__ __nv_bfloat16 g_X_lo[T_TOK * D_MODEL];
__device__ __nv_bfloat16 g_A_hi[T_TOK * ATTN_DIM];     // attn out, [M][K]
__device__ __nv_bfloat16 g_A_lo[T_TOK * ATTN_DIM];
__device__ __nv_bfloat16 g_Wq_hi[QKV_OUT * D_MODEL];   // W_qkv^T, [N][K]
__device__ __nv_bfloat16 g_Wq_lo[QKV_OUT * D_MODEL];
__device__ __nv_bfloat16 g_Wo_hi[D_MODEL * ATTN_DIM];  // W_o^T, [N][K]
__device__ __nv_bfloat16 g_Wo_lo[D_MODEL * ATTN_DIM];

__device__ __nv_bfloat16 g_Qhi[HQ * T_TOK * DH];   // [h][t][d]
__device__ __nv_bfloat16 g_Qlo[HQ * T_TOK * DH];
__device__ __nv_bfloat16 g_Khi[HKV * T_TOK * DH];  // [h][t][d]
__device__ __nv_bfloat16 g_Klo[HKV * T_TOK * DH];
__device__ __nv_bfloat16 g_Vthi[HKV * DH * T_TOK]; // [h][d][t] (transposed)
__device__ __nv_bfloat16 g_Vtlo[HKV * DH * T_TOK];

// ---------------------------------------------------------------------------
// Helpers
// ---------------------------------------------------------------------------
__device__ __forceinline__ uint32_t smem_u32(const void* p) {
    uint32_t a;
    asm("{ .reg .u64 t; cvta.to.shared.u64 t, %1; cvt.u32.u64 %0, t; }"
        : "=r"(a) : "l"(p));
    return a;
}

__device__ __forceinline__ uint32_t lds_u32(uint32_t a) {
    uint32_t v;
    asm volatile("ld.shared.b32 %0, [%1];" : "=r"(v) : "r"(a));
    return v;
}

#define CP_ASYNC16(saddr, gptr) \
    asm volatile("cp.async.cg.shared.global [%0], [%1], 16;" \
                 :: "r"(saddr), "l"(gptr))
#define CP_COMMIT() asm volatile("cp.async.commit_group;" ::: "memory")
#define CP_WAIT(n)  asm volatile("cp.async.wait_group %0;" :: "n"(n) : "memory")

__device__ __forceinline__ void mma_bf16(float* c, const uint32_t* a,
                                         const uint32_t* b) {
    asm volatile(
        "mma.sync.aligned.m16n8k16.row.col.f32.bf16.bf16.f32 "
        "{%0,%1,%2,%3}, {%4,%5,%6,%7}, {%8,%9}, {%0,%1,%2,%3};"
        : "+f"(c[0]), "+f"(c[1]), "+f"(c[2]), "+f"(c[3])
        : "r"(a[0]), "r"(a[1]), "r"(a[2]), "r"(a[3]),
          "r"(b[0]), "r"(b[1]));
}

__device__ __forceinline__ uint32_t pack_bf16x2(float lo, float hi) {
    __nv_bfloat162 h = __floats2bfloat162_rn(lo, hi);   // x=lo (low 16 bits)
    return *reinterpret_cast<uint32_t*>(&h);
}
__device__ __forceinline__ float bf_res(float f) {
    return f - __bfloat162float(__float2bfloat16(f));
}

// ---------------------------------------------------------------------------
// Prep kernels
// ---------------------------------------------------------------------------
__global__ void convert_split_kernel(const float* __restrict__ in,
                                     __nv_bfloat16* __restrict__ hi,
                                     __nv_bfloat16* __restrict__ lo, int n2)
{
    int i = blockIdx.x * blockDim.x + threadIdx.x;
    if (i >= n2) return;
    float2 v = ((const float2*)in)[i];
    __nv_bfloat16 h0 = __float2bfloat16(v.x);
    __nv_bfloat16 h1 = __float2bfloat16(v.y);
    __nv_bfloat162 hh; hh.x = h0; hh.y = h1;
    __nv_bfloat162 ll;
    ll.x = __float2bfloat16(v.x - __bfloat162float(h0));
    ll.y = __float2bfloat16(v.y - __bfloat162float(h1));
    ((__nv_bfloat162*)hi)[i] = hh;
    ((__nv_bfloat162*)lo)[i] = ll;
}

__global__ void transpose_split_kernel(const float* __restrict__ in,
                                       __nv_bfloat16* __restrict__ hi,
                                       __nv_bfloat16* __restrict__ lo,
                                       int R, int C)
{
    __shared__ float t[32][33];
    int c0 = blockIdx.x * 32, r0 = blockIdx.y * 32;
    int tx = threadIdx.x, ty = threadIdx.y;
    #pragma unroll
    for (int j = ty; j < 32; j += 8)
        t[j][tx] = in[(size_t)(r0 + j) * C + c0 + tx];
    __syncthreads();
    #pragma unroll
    for (int j = ty; j < 32; j += 8) {
        float v = t[tx][j];
        __nv_bfloat16 h = __float2bfloat16(v);
        size_t o = (size_t)(c0 + j) * R + r0 + tx;
        hi[o] = h;
        lo[o] = __float2bfloat16(v - __bfloat162float(h));
    }
}

// ---------------------------------------------------------------------------
// mma.sync bf16x3 GEMM: C[M,N] = A[M,K] @ B[N,K]^T (+bias), fp32 out
// Block 128x128, BK=32, 8 warps, 2-stage cp.async pipeline, 2 CTAs/SM.
// ---------------------------------------------------------------------------
#define GSTAGE 40960
#define GEMM_SMEM (2 * GSTAGE)

__global__ __launch_bounds__(256, 2) void gemm_mma_bf16x3(
    const __nv_bfloat16* __restrict__ Ahi, const __nv_bfloat16* __restrict__ Alo,
    const __nv_bfloat16* __restrict__ Bhi, const __nv_bfloat16* __restrict__ Blo,
    const float* __restrict__ bias, float* __restrict__ C,
    int M, int N, int K)
{
    extern __shared__ char dsm[];
    const int tid  = threadIdx.x;
    const int lane = tid & 31, wid = tid >> 5;
    const int wm = wid & 3;
    const int wn = wid >> 2;
    const int g  = lane >> 2, t = lane & 3;
    const int m0 = blockIdx.y * 128, n0 = blockIdx.x * 128;

    const uint32_t sbase = smem_u32(dsm);

    float acc[2][8][4];
    #pragma unroll
    for (int mt = 0; mt < 2; mt++)
        #pragma unroll
        for (int nt = 0; nt < 8; nt++)
            #pragma unroll
            for (int j = 0; j < 4; j++) acc[mt][nt][j] = 0.0f;

    const int niter = K / 32;

    #define LOAD_STAGE(it) do {                                               \
        int _st = (it) & 1; int _kb = (it) * 32;                              \
        uint32_t _s0 = sbase + _st * GSTAGE;                                  \
        _Pragma("unroll")                                                     \
        for (int _c = tid; _c < 512; _c += 256) {                             \
            int _row = _c >> 2, _c8 = _c & 3;                                 \
            uint32_t _so = (uint32_t)(_row * 80 + _c8 * 16);                  \
            size_t _ga = (size_t)(m0 + _row) * K + _kb + _c8 * 8;             \
            size_t _gb = (size_t)(n0 + _row) * K + _kb + _c8 * 8;             \
            CP_ASYNC16(_s0 + _so,          Ahi + _ga);                        \
            CP_ASYNC16(_s0 + 10240 + _so,  Alo + _ga);                        \
            CP_ASYNC16(_s0 + 20480 + _so,  Bhi + _gb);                        \
            CP_ASYNC16(_s0 + 30720 + _so,  Blo + _gb);                        \
        }                                                                     \
        CP_COMMIT();                                                          \
    } while (0)

    LOAD_STAGE(0);
    LOAD_STAGE(1);

    for (int it = 0; it < niter; it++) {
        CP_WAIT(1);
        __syncthreads();

        const uint32_t s0 = sbase + (it & 1) * GSTAGE;
        #pragma unroll
        for (int ks = 0; ks < 2; ks++) {
            const uint32_t koff = (uint32_t)(ks * 32 + t * 4);
            const uint32_t aB = s0 + (uint32_t)((wm * 32 + g) * 80) + koff;
            const uint32_t bB = s0 + 20480u + (uint32_t)((wn * 64 + g) * 80) + koff;

            uint32_t a[2][4], bhi[8][2], bl[8][2];

            #pragma unroll
            for (int mt = 0; mt < 2; mt++) {
                uint32_t ab = aB + (uint32_t)(mt * 16 * 80);
                a[mt][0] = lds_u32(ab);
                a[mt][1] = lds_u32(ab + 640);
                a[mt][2] = lds_u32(ab + 16);
                a[mt][3] = lds_u32(ab + 656);
            }
            #pragma unroll
            for (int nt = 0; nt < 8; nt++) {
                uint32_t bb = bB + (uint32_t)(nt * 8 * 80);
                bhi[nt][0] = lds_u32(bb);
                bhi[nt][1] = lds_u32(bb + 16);
            }
            #pragma unroll
            for (int mt = 0; mt < 2; mt++)
                #pragma unroll
                for (int nt = 0; nt < 8; nt++)
                    mma_bf16(acc[mt][nt], a[mt], bhi[nt]);

            #pragma unroll
            for (int nt = 0; nt < 8; nt++) {
                uint32_t bb = bB + 10240u + (uint32_t)(nt * 8 * 80);
                bl[nt][0] = lds_u32(bb);
                bl[nt][1] = lds_u32(bb + 16);
            }
            #pragma unroll
            for (int mt = 0; mt < 2; mt++)
                #pragma unroll
                for (int nt = 0; nt < 8; nt++)
                    mma_bf16(acc[mt][nt], a[mt], bl[nt]);

            #pragma unroll
            for (int mt = 0; mt < 2; mt++) {
                uint32_t ab = aB + 10240u + (uint32_t)(mt * 16 * 80);
                a[mt][0] = lds_u32(ab);
                a[mt][1] = lds_u32(ab + 640);
                a[mt][2] = lds_u32(ab + 16);
                a[mt][3] = lds_u32(ab + 656);
            }
            #pragma unroll
            for (int mt = 0; mt < 2; mt++)
                #pragma unroll
                for (int nt = 0; nt < 8; nt++)
                    mma_bf16(acc[mt][nt], a[mt], bhi[nt]);
        }
        __syncthreads();

        if (it + 2 < niter) LOAD_STAGE(it + 2);
        else CP_COMMIT();
    }

    const bool hasb = (bias != nullptr);
    #pragma unroll
    for (int mt = 0; mt < 2; mt++) {
        int row0 = m0 + wm * 32 + mt * 16 + g;
        #pragma unroll
        for (int nt = 0; nt < 8; nt++) {
            int col = n0 + wn * 64 + nt * 8 + t * 2;
            float bx = hasb ? bias[col] : 0.0f;
            float by = hasb ? bias[col + 1] : 0.0f;
            float2 v0, v1;
            v0.x = acc[mt][nt][0] + bx; v0.y = acc[mt][nt][1] + by;
            v1.x = acc[mt][nt][2] + bx; v1.y = acc[mt][nt][3] + by;
            *(float2*)(C + (size_t)row0 * N + col) = v0;
            *(float2*)(C + (size_t)(row0 + 8) * N + col) = v1;
        }
    }
    #undef LOAD_STAGE
}

// ---------------------------------------------------------------------------
// RoPE table + Q/K rope-split + V transpose-split
// ---------------------------------------------------------------------------
__global__ void rope_table_kernel(const int* __restrict__ positions)
{
    int idx = blockIdx.x * blockDim.x + threadIdx.x;
    if (idx >= T_TOK * (DH/2)) return;
    int t = idx >> 6;
    int i = idx & 63;
    double inv = pow(1.0e6, -(double)i / 64.0);
    double ang = (double)positions[t] * inv;
    g_rope_cos[idx] = (float)cos(ang);
    g_rope_sin[idx] = (float)sin(ang);
}

__global__ void ropesplit_qk_kernel(const float* __restrict__ qkv)
{
    int t = blockIdx.x;
    int head = blockIdx.y * blockDim.y + threadIdx.y;  // 0..31
    int i = threadIdx.x;                               // 0..63
    float c = g_rope_cos[t * 64 + i];
    float s = g_rope_sin[t * 64 + i];
    size_t src = (size_t)t * QKV_OUT + head * DH;
    float x1 = qkv[src + i];
    float x2 = qkv[src + 64 + i];
    float y1 = x1 * c - x2 * s;
    float y2 = x2 * c + x1 * s;
    __nv_bfloat16 h1 = __float2bfloat16(y1);
    __nv_bfloat16 h2 = __float2bfloat16(y2);
    if (head < HQ) {
        size_t base = ((size_t)head * T_TOK + t) * DH;
        g_Qhi[base + i]      = h1;
        g_Qlo[base + i]      = __float2bfloat16(y1 - __bfloat162float(h1));
        g_Qhi[base + 64 + i] = h2;
        g_Qlo[base + 64 + i] = __float2bfloat16(y2 - __bfloat162float(h2));
    } else {
        size_t base = ((size_t)(head - HQ) * T_TOK + t) * DH;
        g_Khi[base + i]      = h1;
        g_Klo[base + i]      = __float2bfloat16(y1 - __bfloat162float(h1));
        g_Khi[base + 64 + i] = h2;
        g_Klo[base + 64 + i] = __float2bfloat16(y2 - __bfloat162float(h2));
    }
}

__global__ void vsplit_t_kernel(const float* __restrict__ qkv)
{
    __shared__ float tl[32][33];
    int t0 = blockIdx.x * 32, dg0 = blockIdx.y * 32;
    int tx = threadIdx.x, ty = threadIdx.y;
    #pragma unroll
    for (int j = ty; j < 32; j += 8)
        tl[j][tx] = qkv[(size_t)(t0 + j) * QKV_OUT + 4096 + dg0 + tx];
    __syncthreads();
    #pragma unroll
    for (int j = ty; j < 32; j += 8) {
        float v = tl[tx][j];
        __nv_bfloat16 h = __float2bfloat16(v);
        size_t o = (size_t)(dg0 + j) * T_TOK + t0 + tx;
        g_Vthi[o] = h;
        g_Vtlo[o] = __float2bfloat16(v - __bfloat162float(h));
    }
}

// ---------------------------------------------------------------------------
// Tensor-core flash attention (bf16x3 on both GEMMs), causal, GQA.
// Block: 128 q-rows x 1 head. 8 warps, each owns 16 q-rows. KV block 64.
// Grid: (h fastest, qb reversed) so heaviest blocks are scheduled first (LPT).
// ---------------------------------------------------------------------------
#define AQ_BYTES   34816                 // 128*272
#define ASTAGE     71680                 // 2*64*272 + 2*128*144
#define ATT_SMEM   (2*AQ_BYTES + 2*ASTAGE)   // 212992

__global__ __launch_bounds__(256, 1) void attn_mma_kernel(
    const __nv_bfloat16* __restrict__ Qhi, const __nv_bfloat16* __restrict__ Qlo,
    const __nv_bfloat16* __restrict__ Khi, const __nv_bfloat16* __restrict__ Klo,
    const __nv_bfloat16* __restrict__ Vthi, const __nv_bfloat16* __restrict__ Vtlo,
    __nv_bfloat16* __restrict__ Ohi, __nv_bfloat16* __restrict__ Olo)
{
    extern __shared__ char dsm[];
    const uint32_t sb = smem_u32(dsm);
    const uint32_t uQhi = sb, uQlo = sb + AQ_BYTES;
    const uint32_t stage0 = sb + 2 * AQ_BYTES;

    const int qb = (T_TOK / 128 - 1) - blockIdx.y;   // heavy blocks first
    const int h  = blockIdx.x;
    const int kvh = h / GQA_G;
    const int q0 = qb * 128;
    const int tid = threadIdx.x;
    const int w = tid >> 5, lane = tid & 31;
    const int g = lane >> 2, t = lane & 3;

    for (int c = tid; c < 4096; c += 256) {
        int half = (c < 2048) ? 0 : 1;
        int j = c & 2047;
        int r = j >> 4, ch = j & 15;
        uint32_t sa = (half ? uQlo : uQhi) + (uint32_t)(r * 272 + ch * 16);
        const __nv_bfloat16* src = half ? Qlo : Qhi;
        CP_ASYNC16(sa, src + ((size_t)(h * T_TOK + q0 + r) * DH + ch * 8));
    }
    CP_COMMIT();

    const int nkb = 2 * qb + 2;

    #define LOADKV(kb_) do {                                                      \
        uint32_t _st = stage0 + ((kb_) & 1) * ASTAGE;                             \
        const int _kv0 = (kb_) * 64;                                              \
        for (int _c = tid; _c < 4096; _c += 256) {                                \
            if (_c < 2048) {                                                      \
                int _lo = (_c >= 1024); int _j = _c & 1023;                       \
                int _r = _j >> 4, _ch = _j & 15;                                  \
                uint32_t _sa = _st + (_lo ? 17408u : 0u)                          \
                             + (uint32_t)(_r * 272 + _ch * 16);                   \
                const __nv_bfloat16* _s = _lo ? Klo : Khi;                        \
                CP_ASYNC16(_sa, _s + ((size_t)(kvh * T_TOK + _kv0 + _r) * DH      \
                                      + _ch * 8));                                \
            } else {                                                              \
                int _i = _c - 2048;                                               \
                int _lo = (_i >= 1024); int _j = _i & 1023;                       \
                int _d = _j >> 3, _ch = _j & 7;                                   \
                uint32_t _sa = _st + 34816u + (_lo ? 18432u : 0u)                 \
                             + (uint32_t)(_d * 144 + _ch * 16);                   \
                const __nv_bfloat16* _s = _lo ? Vtlo : Vthi;                      \
                CP_ASYNC16(_sa, _s + ((size_t)(kvh * DH + _d) * T_TOK             \
                                      + _kv0 + _ch * 8));                         \
            }                                                                     \
        }                                                                         \
        CP_COMMIT();                                                              \
    } while (0)

    LOADKV(0);
    LOADKV(1);

    float o_[16][4];
    #pragma unroll
    for (int v = 0; v < 16; v++)
        #pragma unroll
        for (int j = 0; j < 4; j++) o_[v][j] = 0.0f;
    float m0 = -1e30f, m1 = -1e30f, l0 = 0.0f, l1 = 0.0f;

    const int qrow0 = q0 + w * 16 + g;
    const int qrow1 = qrow0 + 8;

    for (int kb = 0; kb < nkb; kb++) {
        CP_WAIT(1);
        __syncthreads();

        const uint32_t stK = stage0 + (kb & 1) * ASTAGE;
        const uint32_t stV = stK + 34816u;
        const bool skip = (kb == 2 * qb + 1) && (w < 4);

        if (!skip) {
            // ---- S = Q K^T (bf16x3) ----
            float s[8][4];
            #pragma unroll
            for (int j = 0; j < 8; j++)
                #pragma unroll
                for (int r = 0; r < 4; r++) s[j][r] = 0.0f;

            const uint32_t aQh0 = uQhi + (uint32_t)((w * 16 + g) * 272 + t * 4);
            const uint32_t aQl0 = uQlo + (uint32_t)((w * 16 + g) * 272 + t * 4);
            const uint32_t bK0  = stK + (uint32_t)(g * 272 + t * 4);

            #pragma unroll 1
            for (int kk = 0; kk < 8; kk++) {
                uint32_t aqh[4], aql[4];
                uint32_t qa = aQh0 + kk * 32;
                aqh[0] = lds_u32(qa);        aqh[1] = lds_u32(qa + 2176);
                aqh[2] = lds_u32(qa + 16);   aqh[3] = lds_u32(qa + 2192);
                uint32_t ql = aQl0 + kk * 32;
                aql[0] = lds_u32(ql);        aql[1] = lds_u32(ql + 2176);
                aql[2] = lds_u32(ql + 16);   aql[3] = lds_u32(ql + 2192);

                #pragma unroll
                for (int j = 0; j < 8; j++) {
                    uint32_t kb_off = bK0 + (uint32_t)(j * 8 * 272) + kk * 32;
                    uint32_t bkh[2], bkl[2];
                    bkh[0] = lds_u32(kb_off);
                    bkh[1] = lds_u32(kb_off + 16);
                    bkl[0] = lds_u32(kb_off + 17408);
                    bkl[1] = lds_u32(kb_off + 17424);
                    mma_bf16(s[j], aqh, bkh);
                    mma_bf16(s[j], aqh, bkl);
                    mma_bf16(s[j], aql, bkh);
                }
            }

            // ---- scale + causal mask ----
            const bool pmask = (kb >= 2 * qb);
            #pragma unroll
            for (int j = 0; j < 8; j++) {
                #pragma unroll
                for (int r = 0; r < 4; r++) {
                    float v = s[j][r] * SM_SCALE;
                    if (pmask) {
                        int col = kb * 64 + j * 8 + 2 * t + (r & 1);
                        int row = (r < 2) ? qrow0 : qrow1;
                        if (col > row) v = -1e9f;
                    }
                    s[j][r] = v;
                }
            }

            // ---- online softmax ----
            float mx0 = -1e30f, mx1 = -1e30f;
            #pragma unroll
            for (int j = 0; j < 8; j++) {
                mx0 = fmaxf(mx0, fmaxf(s[j][0], s[j][1]));
                mx1 = fmaxf(mx1, fmaxf(s[j][2], s[j][3]));
            }
            mx0 = fmaxf(mx0, __shfl_xor_sync(0xffffffffu, mx0, 1));
            mx0 = fmaxf(mx0, __shfl_xor_sync(0xffffffffu, mx0, 2));
            mx1 = fmaxf(mx1, __shfl_xor_sync(0xffffffffu, mx1, 1));
            mx1 = fmaxf(mx1, __shfl_xor_sync(0xffffffffu, mx1, 2));

            float mn0 = fmaxf(m0, mx0), mn1 = fmaxf(m1, mx1);
            float a0 = __expf(m0 - mn0), a1 = __expf(m1 - mn1);
            m0 = mn0; m1 = mn1;

            float rs0 = 0.0f, rs1 = 0.0f;
            #pragma unroll
            for (int j = 0; j < 8; j++) {
                s[j][0] = __expf(s[j][0] - mn0);
                s[j][1] = __expf(s[j][1] - mn0);
                s[j][2] = __expf(s[j][2] - mn1);
                s[j][3] = __expf(s[j][3] - mn1);
                rs0 += s[j][0] + s[j][1];
                rs1 += s[j][2] + s[j][3];
            }
            rs0 += __shfl_xor_sync(0xffffffffu, rs0, 1);
            rs0 += __shfl_xor_sync(0xffffffffu, rs0, 2);
            rs1 += __shfl_xor_sync(0xffffffffu, rs1, 1);
            rs1 += __shfl_xor_sync(0xffffffffu, rs1, 2);
            l0 = l0 * a0 + rs0;
            l1 = l1 * a1 + rs1;

            #pragma unroll
            for (int v = 0; v < 16; v++) {
                o_[v][0] *= a0; o_[v][1] *= a0;
                o_[v][2] *= a1; o_[v][3] *= a1;
            }

            // ---- pack P into A-fragments (hi/lo) ----
            uint32_t aPhi[4][4], aPlo[4][4];
            #pragma unroll
            for (int u = 0; u < 4; u++) {
                aPhi[u][0] = pack_bf16x2(s[2*u][0],   s[2*u][1]);
                aPhi[u][1] = pack_bf16x2(s[2*u][2],   s[2*u][3]);
                aPhi[u][2] = pack_bf16x2(s[2*u+1][0], s[2*u+1][1]);
                aPhi[u][3] = pack_bf16x2(s[2*u+1][2], s[2*u+1][3]);
                aPlo[u][0] = pack_bf16x2(bf_res(s[2*u][0]),   bf_res(s[2*u][1]));
                aPlo[u][1] = pack_bf16x2(bf_res(s[2*u][2]),   bf_res(s[2*u][3]));
                aPlo[u][2] = pack_bf16x2(bf_res(s[2*u+1][0]), bf_res(s[2*u+1][1]));
                aPlo[u][3] = pack_bf16x2(bf_res(s[2*u+1][2]), bf_res(s[2*u+1][3]));
            }

            // ---- O += P V (bf16x3) ----
            const uint32_t bV0 = stV + (uint32_t)(g * 144 + t * 4);
            #pragma unroll
            for (int v = 0; v < 16; v++) {
                uint32_t vb = bV0 + (uint32_t)(v * 8 * 144);
                #pragma unroll
                for (int u = 0; u < 4; u++) {
                    uint32_t va = vb + u * 32;
                    uint32_t bh[2], bl[2];
                    bh[0] = lds_u32(va);
                    bh[1] = lds_u32(va + 16);
                    bl[0] = lds_u32(va + 18432);
                    bl[1] = lds_u32(va + 18448);
                    mma_bf16(o_[v], aPhi[u], bh);
                    mma_bf16(o_[v], aPhi[u], bl);
                    mma_bf16(o_[v], aPlo[u], bh);
                }
            }
        }

        __syncthreads();
        if (kb + 2 < nkb) LOADKV(kb + 2);
        else CP_COMMIT();
    }

    // ---- epilogue ----
    float inv0 = 1.0f / l0, inv1 = 1.0f / l1;
    #pragma unroll
    for (int v = 0; v < 16; v++) {
        int d = v * 8 + 2 * t;
        float c0 = o_[v][0] * inv0, c1 = o_[v][1] * inv0;
        float c2 = o_[v][2] * inv1, c3 = o_[v][3] * inv1;
        size_t off0 = (size_t)qrow0 * ATTN_DIM + h * DH + d;
        size_t off1 = (size_t)qrow1 * ATTN_DIM + h * DH + d;
        *(uint32_t*)(Ohi + off0) = pack_bf16x2(c0, c1);
        *(uint32_t*)(Olo + off0) = pack_bf16x2(bf_res(c0), bf_res(c1));
        *(uint32_t*)(Ohi + off1) = pack_bf16x2(c2, c3);
        *(uint32_t*)(Olo + off1) = pack_bf16x2(bf_res(c2), bf_res(c3));
    }
    #undef LOADKV
}

// ---------------------------------------------------------------------------
// Launch
// ---------------------------------------------------------------------------
extern "C" void kernel_launch(void* const* d_in, const int* in_sizes, int n_in,
                              void* d_out, int out_size)
{
    const int*   positions = (const int*)  d_in[0];
    const float* hidden    = (const float*)d_in[1];
    const float* W_qkv     = (const float*)d_in[2];
    const float* b_qkv     = (const float*)d_in[3];
    const float* W_o       = (const float*)d_in[4];
    float* out = (float*)d_out;

    float* qkv;  cudaGetSymbolAddress((void**)&qkv, g_qkv);
    __nv_bfloat16 *Xhi, *Xlo, *Ahi, *Alo, *Wqh, *Wql, *Woh, *Wol;
    __nv_bfloat16 *Qhi, *Qlo, *Khi, *Klo, *Vthi, *Vtlo;
    cudaGetSymbolAddress((void**)&Xhi, g_X_hi);
    cudaGetSymbolAddress((void**)&Xlo, g_X_lo);
    cudaGetSymbolAddress((void**)&Ahi, g_A_hi);
    cudaGetSymbolAddress((void**)&Alo, g_A_lo);
    cudaGetSymbolAddress((void**)&Wqh, g_Wq_hi);
    cudaGetSymbolAddress((void**)&Wql, g_Wq_lo);
    cudaGetSymbolAddress((void**)&Woh, g_Wo_hi);
    cudaGetSymbolAddress((void**)&Wol, g_Wo_lo);
    cudaGetSymbolAddress((void**)&Qhi, g_Qhi);
    cudaGetSymbolAddress((void**)&Qlo, g_Qlo);
    cudaGetSymbolAddress((void**)&Khi, g_Khi);
    cudaGetSymbolAddress((void**)&Klo, g_Klo);
    cudaGetSymbolAddress((void**)&Vthi, g_Vthi);
    cudaGetSymbolAddress((void**)&Vtlo, g_Vtlo);

    cudaFuncSetAttribute(gemm_mma_bf16x3,
                         cudaFuncAttributeMaxDynamicSharedMemorySize, GEMM_SMEM);
    cudaFuncSetAttribute(attn_mma_kernel,
                         cudaFuncAttributeMaxDynamicSharedMemorySize, ATT_SMEM);

    // 0) rope table + hidden/weight splits
    {
        int n = T_TOK * (DH / 2);
        rope_table_kernel<<<(n + 255) / 256, 256>>>(positions);
        int n2 = T_TOK * D_MODEL / 2;
        convert_split_kernel<<<(n2 + 255)/256, 256>>>(hidden, Xhi, Xlo, n2);
        dim3 b1(32, 8);
        dim3 g1(QKV_OUT/32, D_MODEL/32);
        transpose_split_kernel<<<g1, b1>>>(W_qkv, Wqh, Wql, D_MODEL, QKV_OUT);
        dim3 g2(D_MODEL/32, ATTN_DIM/32);
        transpose_split_kernel<<<g2, b1>>>(W_o, Woh, Wol, ATTN_DIM, D_MODEL);
    }

    // 1) QKV projection
    {
        dim3 grid(QKV_OUT / 128, T_TOK / 128);
        gemm_mma_bf16x3<<<grid, 256, GEMM_SMEM>>>(
            Xhi, Xlo, Wqh, Wql, b_qkv, qkv, T_TOK, QKV_OUT, D_MODEL);
    }

    // 2) rope+split Q/K, transpose+split V
    {
        dim3 grid(T_TOK, 8), block(64, 4);
        ropesplit_qk_kernel<<<grid, block>>>(qkv);
        dim3 gv(T_TOK/32, (HKV*DH)/32), bv(32, 8);
        vsplit_t_kernel<<<gv, bv>>>(qkv);
    }

    // 3) tensor-core flash attention (heavy blocks first)
    {
        dim3 grid(HQ, T_TOK / 128);
        attn_mma_kernel<<<grid, 256, ATT_SMEM>>>(
            Qhi, Qlo, Khi, Klo, Vthi, Vtlo, Ahi, Alo);
    }

    // 4) O projection
    {
        dim3 grid(D_MODEL / 128, T_TOK / 128);
        gemm_mma_bf16x3<<<grid, 256, GEMM_SMEM>>>(
            Ahi, Alo, Woh, Wol, nullptr, out, T_TOK, D_MODEL, ATTN_DIM);
    }
}